// round 4
// baseline (speedup 1.0000x reference)
#include <cuda_runtime.h>
#include <math.h>

#define S_SAMPLES 512
#define VDIM      128
#define NVOX      (VDIM * VDIM * VDIM)   // 2097152
#define DET       128
#define NPIX      (DET * DET)            // 16384
#define KSPLIT    4                      // sample-range split for bp occupancy

// 4 binary occupancy volumes, slice = batch*2 + view (view 0 = frontal, 1 = lateral).
// Frontal volumes use TRANSPOSED layout (vx, vz, vy) so warp-lane scatter stores
// (lanes differ in vy) are contiguous. Lateral volumes use natural (vx, vy, vz)
// (lanes differ in vz -> already contiguous).
// Invariant: g_vol is all-zero at entry to kernel_launch (static init + the
// reduce kernel consumes-and-rezeroes every byte it reads).
__device__ __align__(16) unsigned char g_vol[4][NVOX];   // 8 MB
__device__ double       g_acc = 0.0;
__device__ unsigned int g_ctr = 0;

// ---------------------------------------------------------------------------
// Backprojection: one thread per (ray, k-quarter); clip sample range to the
// voxel box, then march IN VOXEL SPACE (q(t) affine in t) writing idempotent 1s.
// blockIdx: x = ray chunk, y = slice (batch*2+view), z = k-quarter.
// ---------------------------------------------------------------------------
__global__ void bp_kernel(const float* __restrict__ predF,
                          const float* __restrict__ predL,
                          const float* __restrict__ srcF,
                          const float* __restrict__ tgtF,
                          const float* __restrict__ srcL,
                          const float* __restrict__ tgtL,
                          const float* __restrict__ Ainv,
                          const float* __restrict__ tinv)
{
    int p = blockIdx.x * blockDim.x + threadIdx.x;
    if (p >= NPIX) return;
    int slice = blockIdx.y;          // 0..3
    int view  = slice & 1;           // 0 = frontal, 1 = lateral
    int batch = slice >> 1;

    const float* mask = (view ? predL : predF) + batch * NPIX;
    if (!(mask[p] > 0.5f)) return;   // inactive pixel: nothing to do

    const float* src = view ? srcL : srcF;
    const float* tgt = (view ? tgtL : tgtF) + 3 * p;

    float sx = src[0], sy = src[1], sz = src[2];
    float dx = tgt[0] - sx, dy = tgt[1] - sy, dz = tgt[2] - sz;
    float len = sqrtf(dx * dx + dy * dy + dz * dz);
    float inv = 1.0f / (len + 1e-8f);
    dx *= inv; dy *= inv; dz *= inv;
    float L = len * 2.5f;

    float a00 = Ainv[0], a01 = Ainv[1], a02 = Ainv[2];
    float a10 = Ainv[3], a11 = Ainv[4], a12 = Ainv[5];
    float a20 = Ainv[6], a21 = Ainv[7], a22 = Ainv[8];

    // Voxel-space ray: q(t) = q0 + t*qd   (affine in t)
    float q0x = a00 * sx + a01 * sy + a02 * sz + tinv[0];
    float q0y = a10 * sx + a11 * sy + a12 * sz + tinv[1];
    float q0z = a20 * sx + a21 * sy + a22 * sz + tinv[2];
    float qdx = a00 * dx + a01 * dy + a02 * dz;
    float qdy = a10 * dx + a11 * dy + a12 * dz;
    float qdz = a20 * dx + a21 * dy + a22 * dz;

    const float LOQ = -0.501f;                  // round() valid window with margin
    const float HIQ = (float)VDIM - 0.499f;
    float tlo = 0.0f, thi = L;
    {
        float q0a[3] = {q0x, q0y, q0z};
        float qda[3] = {qdx, qdy, qdz};
        #pragma unroll
        for (int ax = 0; ax < 3; ax++) {
            float q0 = q0a[ax], qd = qda[ax];
            if (fabsf(qd) < 1e-9f) {
                if (q0 < LOQ || q0 > HIQ) { tlo = 1.0f; thi = 0.0f; }
            } else {
                float u1 = (LOQ - q0) / qd;
                float u2 = (HIQ - q0) / qd;
                tlo = fmaxf(tlo, fminf(u1, u2));
                thi = fminf(thi, fmaxf(u1, u2));
            }
        }
    }
    if (thi < tlo) return;

    float dt = L * (1.0f / (S_SAMPLES - 1));
    int klo = max(0,             (int)floorf(tlo / dt) - 2);   // safety margin:
    int khi = min(S_SAMPLES - 1, (int)ceilf (thi / dt) + 2);   // per-sample check authoritative

    // Restrict to this block's static k-quarter.
    int kq0 = blockIdx.z * (S_SAMPLES / KSPLIT);
    klo = max(klo, kq0);
    khi = min(khi, kq0 + (S_SAMPLES / KSPLIT) - 1);
    if (khi < klo) return;

    // Pre-scale direction by L: q = fma(tv, rd, q0), tv = k/(S-1)
    float rdx = L * qdx, rdy = L * qdy, rdz = L * qdz;
    const float c1 = 1.0f / (S_SAMPLES - 1);

    unsigned char* vol = g_vol[slice];
    for (int k = klo; k <= khi; k++) {
        float tv = (float)k * c1;                      // matches jnp.linspace(0,1,S)
        int vx = __float2int_rn(fmaf(tv, rdx, q0x));   // F2I.rn = ties-to-even (jnp.round)
        int vy = __float2int_rn(fmaf(tv, rdy, q0y));
        int vz = __float2int_rn(fmaf(tv, rdz, q0z));
        if ((unsigned)vx < (unsigned)VDIM &&
            (unsigned)vy < (unsigned)VDIM &&
            (unsigned)vz < (unsigned)VDIM) {
            // view 0 (frontal): transposed (vx, vz, vy) -> lanes contiguous in vy
            // view 1 (lateral): natural    (vx, vy, vz) -> lanes contiguous in vz
            int idx = view ? ((vx * VDIM + vy) * VDIM + vz)
                           : ((vx * VDIM + vz) * VDIM + vy);
            vol[idx] = 1;   // idempotent racy store
        }
    }
}

// ---------------------------------------------------------------------------
// BCE + finalize + volume re-zero, fused.
//   s = volF+volL in {0,1,2};  term = b[s] + g*s,  b[s] = log(1 - sigmoid(s)).
// Grid = 128 planes x 4 vy-quarters, 512 threads (16 warps) per block.
// Frontal volumes (stored (vx, vz, vy)) are transposed through smem:
//   phase 1 writes sT[vy_local][vz] (byte column-writes; same-word merges),
//   phase 2 reads one aligned conflict-free LDS.32 per 4-vz group.
// Every byte of g_vol read here is immediately re-zeroed for the next call.
// ---------------------------------------------------------------------------
__device__ __forceinline__ float bce_term(float g, int s) {
    float b = (s == 0) ? -0.69314718055994531f
            : (s == 1) ? -1.31326168751822287f
                       : -2.12692801104297263f;
    return fmaf(g, (float)s, b);
}

__device__ __forceinline__ float warp_sum(float v) {
    #pragma unroll
    for (int o = 16; o > 0; o >>= 1) v += __shfl_down_sync(0xffffffffu, v, o);
    return v;
}

#define TROW 132   // smem row stride (vz 128 + 4 pad): word idx = 33*vy + vz/4

__global__ void __launch_bounds__(512)
reduce_kernel(const float* __restrict__ gt, float* __restrict__ out)
{
    __shared__ unsigned char sT0[32 * TROW];   // frontal batch 0: [vy_local][vz]
    __shared__ unsigned char sT1[32 * TROW];   // frontal batch 1
    __shared__ float sh[16];

    int vx  = blockIdx.x;            // plane
    int vy0 = blockIdx.y * 32;       // vy quarter
    int t   = threadIdx.x;           // 512 threads

    // --- phase 1: load + transpose + zero frontal sub-planes ---------------
    // Global frontal layout byte offset: vx*16384 + vz*128 + vy.
    // Thread t: volume = t>>8; o16 = t&255 -> vz row r = o16>>1, 16B half sub.
    // Warp LDG.128: 16 rows x 32B chunk = 16 sectors (optimal for 512B).
    {
        int volsel = t >> 8;                     // 0 -> F0, 1 -> F1
        int o16 = t & 255;
        int r   = o16 >> 1;
        int sub = o16 & 1;
        size_t go = (size_t)vx * 16384 + (size_t)r * 128 + vy0 + sub * 16;
        uint4 z4; z4.x = z4.y = z4.z = z4.w = 0u;
        uint4* p = reinterpret_cast<uint4*>(g_vol[volsel ? 2 : 0] + go);
        uint4 a = *p; *p = z4;                   // consume-and-reset
        unsigned char ab[16];
        *reinterpret_cast<uint4*>(ab) = a;
        unsigned char* sT = volsel ? sT1 : sT0;
        int vybase = sub * 16;
        #pragma unroll
        for (int i = 0; i < 16; i++) {           // byte column-writes: lanes hit
            sT[(vybase + i) * TROW + r] = ab[i]; // different bytes of same word
        }                                        // -> merged, conflict-free
    }
    __syncthreads();

    // --- phase 2: compute + zero lateral -----------------------------------
    float sum = 0.0f;
    int c = t & 31;          // lane: uchar4 group along vz (vz = 4c..4c+3)
    int w = t >> 5;          // warp 0..15: 2 vy values each
    uchar4 zc; zc.x = zc.y = zc.z = zc.w = 0;
    #pragma unroll
    for (int ii = 0; ii < 2; ii++) {
        int vyl = w * 2 + ii;                    // 0..31
        int vy  = vy0 + vyl;
        int idx4 = vx * 4096 + vy * 32 + c;      // uchar4 / float4 index
        uchar4 L0 = reinterpret_cast<const uchar4*>(g_vol[1])[idx4];
        uchar4 L1 = reinterpret_cast<const uchar4*>(g_vol[3])[idx4];
        reinterpret_cast<uchar4*>(g_vol[1])[idx4] = zc;   // consume-and-reset
        reinterpret_cast<uchar4*>(g_vol[3])[idx4] = zc;
        float4 g = reinterpret_cast<const float4*>(gt)[idx4];
        // one aligned word = frontal bytes vz 4c..4c+3 ; bank = (vyl + c) % 32
        unsigned int f0 = *reinterpret_cast<const unsigned int*>(&sT0[vyl * TROW + 4 * c]);
        unsigned int f1 = *reinterpret_cast<const unsigned int*>(&sT1[vyl * TROW + 4 * c]);
        sum += bce_term(g.x, (int)( f0        & 255u) + L0.x)
             + bce_term(g.x, (int)( f1        & 255u) + L1.x);
        sum += bce_term(g.y, (int)((f0 >>  8) & 255u) + L0.y)
             + bce_term(g.y, (int)((f1 >>  8) & 255u) + L1.y);
        sum += bce_term(g.z, (int)((f0 >> 16) & 255u) + L0.z)
             + bce_term(g.z, (int)((f1 >> 16) & 255u) + L1.z);
        sum += bce_term(g.w, (int)( f0 >> 24        ) + L0.w)
             + bce_term(g.w, (int)( f1 >> 24        ) + L1.w);
    }

    // --- block reduce -> global atomic -> last-block finalize --------------
    sum = warp_sum(sum);
    int lane = t & 31;
    if (lane == 0) sh[w] = sum;
    __syncthreads();
    if (w == 0) {
        float v = (lane < 16) ? sh[lane] : 0.0f;
        v = warp_sum(v);
        if (lane == 0) {
            atomicAdd(&g_acc, (double)v);
            __threadfence();
            unsigned int total = gridDim.x * gridDim.y;
            unsigned int done = atomicInc(&g_ctr, total - 1);   // self-resetting
            if (done == total - 1) {
                double acc = atomicAdd(&g_acc, 0.0);            // atomic read
                out[0] = (float)(-acc / (2.0 * (double)NVOX));  // /B /NVOX
                g_acc = 0.0;                                    // reset for next call
            }
        }
    }
}

// ---------------------------------------------------------------------------
extern "C" void kernel_launch(void* const* d_in, const int* in_sizes, int n_in,
                              void* d_out, int out_size)
{
    const float* predF = (const float*)d_in[0];
    const float* predL = (const float*)d_in[1];
    const float* srcF  = (const float*)d_in[2];
    const float* tgtF  = (const float*)d_in[3];
    const float* srcL  = (const float*)d_in[4];
    const float* tgtL  = (const float*)d_in[5];
    const float* gt    = (const float*)d_in[6];
    const float* Ainv  = (const float*)d_in[7];
    const float* tinv  = (const float*)d_in[8];
    float* out = (float*)d_out;

    dim3 bp_grid((NPIX + 255) / 256, 4, KSPLIT);   // 64 x 4 x 4 = 1024 blocks
    bp_kernel<<<bp_grid, 256>>>(predF, predL, srcF, tgtF, srcL, tgtL, Ainv, tinv);

    dim3 rd_grid(VDIM, 4);                          // 512 blocks x 512 threads
    reduce_kernel<<<rd_grid, 512>>>(gt, out);
}

// round 5
// speedup vs baseline: 1.0111x; 1.0111x over previous
#include <cuda_runtime.h>
#include <math.h>

#define S_SAMPLES 512
#define VDIM      128
#define NVOX      (VDIM * VDIM * VDIM)   // 2097152
#define DET       128
#define NPIX      (DET * DET)            // 16384

// 4 binary occupancy volumes, slice = batch*2 + view (view 0 = frontal, 1 = lateral).
// Frontal volumes use TRANSPOSED layout (vx, vz, vy) so warp-lane scatter stores
// (lanes differ in vy) are contiguous. Lateral volumes use natural (vx, vy, vz)
// (lanes differ in vz -> already contiguous).
// Invariant: g_vol is all-zero at entry to kernel_launch (static init + the
// reduce kernel consumes-and-rezeroes every byte it reads).
__device__ __align__(16) unsigned char g_vol[4][NVOX];   // 8 MB

// Spread accumulators / counters: one 128B line each so L2 atomics from
// different blocks hit distinct LTS slices (no same-address serialization).
struct __align__(128) AccSlot { double v;       char pad[120]; };
struct __align__(128) CtrSlot { unsigned int c; char pad[124]; };
__device__ AccSlot g_accs[32];        // zero-init; finalizer re-zeroes via atomicExch
__device__ CtrSlot g_ctr1[32];        // self-resetting (atomicInc cap)
__device__ unsigned int g_ctr2 = 0;   // self-resetting

// ---------------------------------------------------------------------------
// Backprojection: one thread per ray; clip sample range to the voxel box,
// then march IN VOXEL SPACE (q(t) affine in t) writing idempotent 1s.
// ---------------------------------------------------------------------------
__global__ void bp_kernel(const float* __restrict__ predF,
                          const float* __restrict__ predL,
                          const float* __restrict__ srcF,
                          const float* __restrict__ tgtF,
                          const float* __restrict__ srcL,
                          const float* __restrict__ tgtL,
                          const float* __restrict__ Ainv,
                          const float* __restrict__ tinv)
{
    int p = blockIdx.x * blockDim.x + threadIdx.x;
    if (p >= NPIX) return;
    int slice = blockIdx.y;          // 0..3
    int view  = slice & 1;           // 0 = frontal, 1 = lateral
    int batch = slice >> 1;

    const float* mask = (view ? predL : predF) + batch * NPIX;
    if (!(mask[p] > 0.5f)) return;   // inactive pixel: nothing to do

    const float* src = view ? srcL : srcF;
    const float* tgt = (view ? tgtL : tgtF) + 3 * p;

    float sx = src[0], sy = src[1], sz = src[2];
    float dx = tgt[0] - sx, dy = tgt[1] - sy, dz = tgt[2] - sz;
    float len = sqrtf(dx * dx + dy * dy + dz * dz);
    float inv = 1.0f / (len + 1e-8f);
    dx *= inv; dy *= inv; dz *= inv;
    float L = len * 2.5f;

    float a00 = Ainv[0], a01 = Ainv[1], a02 = Ainv[2];
    float a10 = Ainv[3], a11 = Ainv[4], a12 = Ainv[5];
    float a20 = Ainv[6], a21 = Ainv[7], a22 = Ainv[8];

    // Voxel-space ray: q(t) = q0 + t*qd   (affine in t)
    float q0x = a00 * sx + a01 * sy + a02 * sz + tinv[0];
    float q0y = a10 * sx + a11 * sy + a12 * sz + tinv[1];
    float q0z = a20 * sx + a21 * sy + a22 * sz + tinv[2];
    float qdx = a00 * dx + a01 * dy + a02 * dz;
    float qdy = a10 * dx + a11 * dy + a12 * dz;
    float qdz = a20 * dx + a21 * dy + a22 * dz;

    const float LOQ = -0.501f;                  // round() valid window with margin
    const float HIQ = (float)VDIM - 0.499f;
    float tlo = 0.0f, thi = L;
    {
        float q0a[3] = {q0x, q0y, q0z};
        float qda[3] = {qdx, qdy, qdz};
        #pragma unroll
        for (int ax = 0; ax < 3; ax++) {
            float q0 = q0a[ax], qd = qda[ax];
            if (fabsf(qd) < 1e-9f) {
                if (q0 < LOQ || q0 > HIQ) { tlo = 1.0f; thi = 0.0f; }
            } else {
                float u1 = (LOQ - q0) / qd;
                float u2 = (HIQ - q0) / qd;
                tlo = fmaxf(tlo, fminf(u1, u2));
                thi = fminf(thi, fmaxf(u1, u2));
            }
        }
    }
    if (thi < tlo) return;

    float dt = L * (1.0f / (S_SAMPLES - 1));
    int klo = max(0,             (int)floorf(tlo / dt) - 2);   // safety margin:
    int khi = min(S_SAMPLES - 1, (int)ceilf (thi / dt) + 2);   // per-sample check authoritative

    // Pre-scale direction by L: q = fma(tv, rd, q0), tv = k/(S-1)
    float rdx = L * qdx, rdy = L * qdy, rdz = L * qdz;
    const float c1 = 1.0f / (S_SAMPLES - 1);

    unsigned char* vol = g_vol[slice];
    for (int k = klo; k <= khi; k++) {
        float tv = (float)k * c1;                      // matches jnp.linspace(0,1,S)
        int vx = __float2int_rn(fmaf(tv, rdx, q0x));   // F2I.rn = ties-to-even (jnp.round)
        int vy = __float2int_rn(fmaf(tv, rdy, q0y));
        int vz = __float2int_rn(fmaf(tv, rdz, q0z));
        if ((unsigned)vx < (unsigned)VDIM &&
            (unsigned)vy < (unsigned)VDIM &&
            (unsigned)vz < (unsigned)VDIM) {
            // view 0 (frontal): transposed (vx, vz, vy) -> lanes contiguous in vy
            // view 1 (lateral): natural    (vx, vy, vz) -> lanes contiguous in vz
            int idx = view ? ((vx * VDIM + vy) * VDIM + vz)
                           : ((vx * VDIM + vz) * VDIM + vy);
            vol[idx] = 1;   // idempotent racy store
        }
    }
}

// ---------------------------------------------------------------------------
// BCE + finalize + volume re-zero, fused.
//   s = volF+volL in {0,1,2};  term = b[s] + g*s,  b[s] = log(1 - sigmoid(s)).
// Grid = 128 planes x 4 vy-quarters, 512 threads per block.
// Frontal volumes (stored (vx, vz, vy)) are transposed through smem:
//   phase 1 writes sT[vy_local][vz] (byte column-writes; same-word merges),
//   phase 2 reads one aligned conflict-free LDS.32 per 4-vz group.
// Every byte of g_vol read here is immediately re-zeroed for the next call.
// Tail: spread two-level arrival tree (32 slots x 16 blocks) -> NO
// same-address atomic serialization (was ~12 us of REDG/ATOM queueing).
// ---------------------------------------------------------------------------
__device__ __forceinline__ float bce_term(float g, int s) {
    float b = (s == 0) ? -0.69314718055994531f
            : (s == 1) ? -1.31326168751822287f
                       : -2.12692801104297263f;
    return fmaf(g, (float)s, b);
}

__device__ __forceinline__ float warp_sum(float v) {
    #pragma unroll
    for (int o = 16; o > 0; o >>= 1) v += __shfl_down_sync(0xffffffffu, v, o);
    return v;
}

#define TROW 132   // smem row stride (vz 128 + 4 pad)

__global__ void __launch_bounds__(512)
reduce_kernel(const float* __restrict__ gt, float* __restrict__ out)
{
    __shared__ unsigned char sT0[32 * TROW];   // frontal batch 0: [vy_local][vz]
    __shared__ unsigned char sT1[32 * TROW];   // frontal batch 1
    __shared__ float sh[16];

    int vx  = blockIdx.x;            // plane
    int vy0 = blockIdx.y * 32;       // vy quarter
    int t   = threadIdx.x;           // 512 threads

    // --- phase 1: load + transpose + zero frontal sub-planes ---------------
    // Global frontal layout byte offset: vx*16384 + vz*128 + vy.
    {
        int volsel = t >> 8;                     // 0 -> F0, 1 -> F1
        int o16 = t & 255;
        int r   = o16 >> 1;                      // vz row
        int sub = o16 & 1;                       // 16B half of the 32B vy chunk
        size_t go = (size_t)vx * 16384 + (size_t)r * 128 + vy0 + sub * 16;
        uint4 z4; z4.x = z4.y = z4.z = z4.w = 0u;
        uint4* p = reinterpret_cast<uint4*>(g_vol[volsel ? 2 : 0] + go);
        uint4 a = *p; *p = z4;                   // consume-and-reset
        unsigned char ab[16];
        *reinterpret_cast<uint4*>(ab) = a;
        unsigned char* sT = volsel ? sT1 : sT0;
        int vybase = sub * 16;
        #pragma unroll
        for (int i = 0; i < 16; i++) {           // byte column-writes: lanes hit
            sT[(vybase + i) * TROW + r] = ab[i]; // different bytes of same word
        }                                        // -> merged, conflict-free
    }
    __syncthreads();

    // --- phase 2: compute + zero lateral -----------------------------------
    float sum = 0.0f;
    int c = t & 31;          // lane: uchar4 group along vz (vz = 4c..4c+3)
    int w = t >> 5;          // warp 0..15: 2 vy values each
    uchar4 zc; zc.x = zc.y = zc.z = zc.w = 0;
    #pragma unroll
    for (int ii = 0; ii < 2; ii++) {
        int vyl = w * 2 + ii;                    // 0..31
        int vy  = vy0 + vyl;
        int idx4 = vx * 4096 + vy * 32 + c;      // uchar4 / float4 index
        uchar4 L0 = reinterpret_cast<const uchar4*>(g_vol[1])[idx4];
        uchar4 L1 = reinterpret_cast<const uchar4*>(g_vol[3])[idx4];
        reinterpret_cast<uchar4*>(g_vol[1])[idx4] = zc;   // consume-and-reset
        reinterpret_cast<uchar4*>(g_vol[3])[idx4] = zc;
        float4 g = reinterpret_cast<const float4*>(gt)[idx4];
        unsigned int f0 = *reinterpret_cast<const unsigned int*>(&sT0[vyl * TROW + 4 * c]);
        unsigned int f1 = *reinterpret_cast<const unsigned int*>(&sT1[vyl * TROW + 4 * c]);
        sum += bce_term(g.x, (int)( f0        & 255u) + L0.x)
             + bce_term(g.x, (int)( f1        & 255u) + L1.x);
        sum += bce_term(g.y, (int)((f0 >>  8) & 255u) + L0.y)
             + bce_term(g.y, (int)((f1 >>  8) & 255u) + L1.y);
        sum += bce_term(g.z, (int)((f0 >> 16) & 255u) + L0.z)
             + bce_term(g.z, (int)((f1 >> 16) & 255u) + L1.z);
        sum += bce_term(g.w, (int)( f0 >> 24        ) + L0.w)
             + bce_term(g.w, (int)( f1 >> 24        ) + L1.w);
    }

    // --- block reduce -> spread arrival tree -> last-block finalize ---------
    sum = warp_sum(sum);
    int lane = t & 31;
    if (lane == 0) sh[w] = sum;
    __syncthreads();
    if (w == 0) {
        float v = (lane < 16) ? sh[lane] : 0.0f;
        v = warp_sum(v);
        if (lane == 0) {
            // 512 blocks -> 32 slots x 16 blocks (gridDim.y*128 is 0 mod 32,
            // so slot = blockIdx.x & 31 gives exactly 16 arrivals per slot).
            int slot = blockIdx.x & 31;
            atomicAdd(&g_accs[slot].v, (double)v);     // no-return -> REDG.F64, spread addrs
            __threadfence();
            unsigned int d1 = atomicInc(&g_ctr1[slot].c, 15u);   // self-resetting
            if (d1 == 15u) {
                unsigned int d2 = atomicInc(&g_ctr2, 31u);       // 32 participants only
                if (d2 == 31u) {
                    double acc = 0.0;
                    #pragma unroll
                    for (int i = 0; i < 32; i++) {
                        // atomic read-and-reset through L2 (also preps next call)
                        unsigned long long old = atomicExch(
                            reinterpret_cast<unsigned long long*>(&g_accs[i].v), 0ull);
                        acc += __longlong_as_double(old);
                    }
                    out[0] = (float)(-acc / (2.0 * (double)NVOX));  // /B /NVOX
                }
            }
        }
    }
}

// ---------------------------------------------------------------------------
extern "C" void kernel_launch(void* const* d_in, const int* in_sizes, int n_in,
                              void* d_out, int out_size)
{
    const float* predF = (const float*)d_in[0];
    const float* predL = (const float*)d_in[1];
    const float* srcF  = (const float*)d_in[2];
    const float* tgtF  = (const float*)d_in[3];
    const float* srcL  = (const float*)d_in[4];
    const float* tgtL  = (const float*)d_in[5];
    const float* gt    = (const float*)d_in[6];
    const float* Ainv  = (const float*)d_in[7];
    const float* tinv  = (const float*)d_in[8];
    float* out = (float*)d_out;

    dim3 bp_grid((NPIX + 255) / 256, 4);      // 64 x 4 = 256 blocks (no KSPLIT)
    bp_kernel<<<bp_grid, 256>>>(predF, predL, srcF, tgtF, srcL, tgtL, Ainv, tinv);

    dim3 rd_grid(VDIM, 4);                    // 512 blocks x 512 threads
    reduce_kernel<<<rd_grid, 512>>>(gt, out);
}

// round 6
// speedup vs baseline: 1.3582x; 1.3433x over previous
#include <cuda_runtime.h>
#include <math.h>

#define S_SAMPLES 512
#define VDIM      128
#define NVOX      (VDIM * VDIM * VDIM)   // 2097152
#define DET       128
#define NPIX      (DET * DET)            // 16384

// 4 binary occupancy volumes, slice = batch*2 + view (view 0 = frontal, 1 = lateral).
// Frontal volumes use TRANSPOSED layout (vx, vz, vy) so warp-lane scatter stores
// (lanes differ in vy) are contiguous. Lateral volumes use natural (vx, vy, vz)
// (lanes differ in vz -> already contiguous).
// Invariant: g_vol is all-zero at entry to kernel_launch (static init + the
// reduce kernel consumes-and-rezeroes every byte it reads).
__device__ __align__(16) unsigned char g_vol[4][NVOX];   // 8 MB
__device__ double       g_acc = 0.0;
__device__ unsigned int g_ctr = 0;

// ---------------------------------------------------------------------------
// Backprojection: one thread per ray; clip sample range to the voxel box,
// then march IN VOXEL SPACE (q(t) affine in t) writing idempotent 1s.
// ---------------------------------------------------------------------------
__global__ void bp_kernel(const float* __restrict__ predF,
                          const float* __restrict__ predL,
                          const float* __restrict__ srcF,
                          const float* __restrict__ tgtF,
                          const float* __restrict__ srcL,
                          const float* __restrict__ tgtL,
                          const float* __restrict__ Ainv,
                          const float* __restrict__ tinv)
{
    int p = blockIdx.x * blockDim.x + threadIdx.x;
    if (p >= NPIX) return;
    int slice = blockIdx.y;          // 0..3
    int view  = slice & 1;           // 0 = frontal, 1 = lateral
    int batch = slice >> 1;

    const float* mask = (view ? predL : predF) + batch * NPIX;
    if (!(mask[p] > 0.5f)) return;   // inactive pixel: nothing to do

    const float* src = view ? srcL : srcF;
    const float* tgt = (view ? tgtL : tgtF) + 3 * p;

    float sx = src[0], sy = src[1], sz = src[2];
    float dx = tgt[0] - sx, dy = tgt[1] - sy, dz = tgt[2] - sz;
    float len = sqrtf(dx * dx + dy * dy + dz * dz);
    float inv = 1.0f / (len + 1e-8f);
    dx *= inv; dy *= inv; dz *= inv;
    float L = len * 2.5f;

    float a00 = Ainv[0], a01 = Ainv[1], a02 = Ainv[2];
    float a10 = Ainv[3], a11 = Ainv[4], a12 = Ainv[5];
    float a20 = Ainv[6], a21 = Ainv[7], a22 = Ainv[8];

    // Voxel-space ray: q(t) = q0 + t*qd   (affine in t)
    float q0x = a00 * sx + a01 * sy + a02 * sz + tinv[0];
    float q0y = a10 * sx + a11 * sy + a12 * sz + tinv[1];
    float q0z = a20 * sx + a21 * sy + a22 * sz + tinv[2];
    float qdx = a00 * dx + a01 * dy + a02 * dz;
    float qdy = a10 * dx + a11 * dy + a12 * dz;
    float qdz = a20 * dx + a21 * dy + a22 * dz;

    const float LOQ = -0.501f;                  // round() valid window with margin
    const float HIQ = (float)VDIM - 0.499f;
    float tlo = 0.0f, thi = L;
    {
        float q0a[3] = {q0x, q0y, q0z};
        float qda[3] = {qdx, qdy, qdz};
        #pragma unroll
        for (int ax = 0; ax < 3; ax++) {
            float q0 = q0a[ax], qd = qda[ax];
            if (fabsf(qd) < 1e-9f) {
                if (q0 < LOQ || q0 > HIQ) { tlo = 1.0f; thi = 0.0f; }
            } else {
                float u1 = (LOQ - q0) / qd;
                float u2 = (HIQ - q0) / qd;
                tlo = fmaxf(tlo, fminf(u1, u2));
                thi = fminf(thi, fmaxf(u1, u2));
            }
        }
    }
    if (thi < tlo) return;

    float dt = L * (1.0f / (S_SAMPLES - 1));
    int klo = max(0,             (int)floorf(tlo / dt) - 2);   // safety margin:
    int khi = min(S_SAMPLES - 1, (int)ceilf (thi / dt) + 2);   // per-sample check authoritative

    // Pre-scale direction by L: q = fma(tv, rd, q0), tv = k/(S-1)
    float rdx = L * qdx, rdy = L * qdy, rdz = L * qdz;
    const float c1 = 1.0f / (S_SAMPLES - 1);

    unsigned char* vol = g_vol[slice];
    for (int k = klo; k <= khi; k++) {
        float tv = (float)k * c1;                      // matches jnp.linspace(0,1,S)
        int vx = __float2int_rn(fmaf(tv, rdx, q0x));   // F2I.rn = ties-to-even (jnp.round)
        int vy = __float2int_rn(fmaf(tv, rdy, q0y));
        int vz = __float2int_rn(fmaf(tv, rdz, q0z));
        if ((unsigned)vx < (unsigned)VDIM &&
            (unsigned)vy < (unsigned)VDIM &&
            (unsigned)vz < (unsigned)VDIM) {
            // view 0 (frontal): transposed (vx, vz, vy) -> lanes contiguous in vy
            // view 1 (lateral): natural    (vx, vy, vz) -> lanes contiguous in vz
            int idx = view ? ((vx * VDIM + vy) * VDIM + vz)
                           : ((vx * VDIM + vz) * VDIM + vy);
            vol[idx] = 1;   // idempotent racy store
        }
    }
}

// ---------------------------------------------------------------------------
// BCE + finalize + volume re-zero, fused. 256 threads, grid (128, 4).
//
// Exact decomposition (sF, sL binary):
//   b[sF+sL] + g*(sF+sL) = B0 + (sF+sL)*(CC + g) + KAPPA*(sF & sL)
// with B0 = log(1-sig(0)), CC = b1-b0, KAPPA = b2-2*b1+b0.
// The constant B0 * (2*NVOX) is folded into the finalizer; intersections are
// counted as integers via popc.
//
// ALL global loads are issued up-front (MLP ~14/thread) so the transpose +
// barrier + compute overlap the L2 latency instead of exposing it.
// Every byte of g_vol read here is immediately re-zeroed for the next call.
// ---------------------------------------------------------------------------
#define CC_F    (-0.62011450695827750f)   // b1 - b0
#define KAPPA_F (-0.19355181656647243f)   // b2 - 2*b1 + b0
#define B0_D    (-0.69314718055994531)    // log(0.5)

__device__ __forceinline__ float warp_sum(float v) {
    #pragma unroll
    for (int o = 16; o > 0; o >>= 1) v += __shfl_down_sync(0xffffffffu, v, o);
    return v;
}

#define TROW 132   // smem row stride (vz 128 + 4 pad)

__global__ void __launch_bounds__(256)
reduce_kernel(const float* __restrict__ gt, float* __restrict__ out)
{
    __shared__ unsigned char sT0[32 * TROW];   // frontal batch 0: [vy_local][vz]
    __shared__ unsigned char sT1[32 * TROW];   // frontal batch 1
    __shared__ float sh[8];

    int vx  = blockIdx.x;            // plane
    int vy0 = blockIdx.y * 32;       // vy quarter
    int t   = threadIdx.x;           // 256 threads
    int c   = t & 31;                // lane: word group along vz (vz = 4c..4c+3)
    int w   = t >> 5;                // warp 0..7: 4 vy values each

    // ---- issue ALL global loads up front (max MLP, overlap with transpose) --
    int r   = t >> 1;                // frontal vz row
    int sub = t & 1;                 // 16B half of the 32B vy chunk
    size_t go = (size_t)vx * 16384 + (size_t)r * 128 + vy0 + sub * 16;
    uint4* pF0 = reinterpret_cast<uint4*>(g_vol[0] + go);
    uint4* pF1 = reinterpret_cast<uint4*>(g_vol[2] + go);
    uint4 a = *pF0;                  // frontal batch 0 (16 vy bytes, one vz row)
    uint4 b = *pF1;                  // frontal batch 1

    unsigned int l0w[4], l1w[4];     // lateral words: vz bytes 4c..4c+3
    float4 gv[4];
    int idx4[4];
    #pragma unroll
    for (int ii = 0; ii < 4; ii++) {
        int vyl = w * 4 + ii;                            // 0..31
        idx4[ii] = vx * 4096 + (vy0 + vyl) * 32 + c;     // word / float4 index
        l0w[ii] = reinterpret_cast<const unsigned int*>(g_vol[1])[idx4[ii]];
        l1w[ii] = reinterpret_cast<const unsigned int*>(g_vol[3])[idx4[ii]];
        gv[ii]  = reinterpret_cast<const float4*>(gt)[idx4[ii]];
    }

    // ---- consume-and-reset: zero every byte we just read --------------------
    uint4 z4; z4.x = z4.y = z4.z = z4.w = 0u;
    *pF0 = z4;
    *pF1 = z4;
    #pragma unroll
    for (int ii = 0; ii < 4; ii++) {
        reinterpret_cast<unsigned int*>(g_vol[1])[idx4[ii]] = 0u;
        reinterpret_cast<unsigned int*>(g_vol[3])[idx4[ii]] = 0u;
    }

    // ---- smem transpose of frontal (byte column-writes, same-word merge) ----
    unsigned char ab[16], bb[16];
    *reinterpret_cast<uint4*>(ab) = a;
    *reinterpret_cast<uint4*>(bb) = b;
    int vybase = sub * 16;
    #pragma unroll
    for (int i = 0; i < 16; i++) {
        sT0[(vybase + i) * TROW + r] = ab[i];
        sT1[(vybase + i) * TROW + r] = bb[i];
    }
    __syncthreads();

    // ---- compute (registers + smem only; no exposed global latency) ---------
    float sum  = 0.0f;
    int   icnt = 0;
    #pragma unroll
    for (int ii = 0; ii < 4; ii++) {
        int vyl = w * 4 + ii;
        unsigned int f0 = *reinterpret_cast<const unsigned int*>(&sT0[vyl * TROW + 4 * c]);
        unsigned int f1 = *reinterpret_cast<const unsigned int*>(&sT1[vyl * TROW + 4 * c]);
        unsigned int s0 = f0 + l0w[ii];          // bytewise sums (each <= 2, no carry)
        unsigned int s1 = f1 + l1w[ii];
        icnt += __popc(f0 & l0w[ii]) + __popc(f1 & l1w[ii]);   // intersections
        float cgx = CC_F + gv[ii].x;
        float cgy = CC_F + gv[ii].y;
        float cgz = CC_F + gv[ii].z;
        float cgw = CC_F + gv[ii].w;
        sum = fmaf((float)( s0        & 255u), cgx, sum);
        sum = fmaf((float)((s0 >>  8) & 255u), cgy, sum);
        sum = fmaf((float)((s0 >> 16) & 255u), cgz, sum);
        sum = fmaf((float)( s0 >> 24        ), cgw, sum);
        sum = fmaf((float)( s1        & 255u), cgx, sum);
        sum = fmaf((float)((s1 >>  8) & 255u), cgy, sum);
        sum = fmaf((float)((s1 >> 16) & 255u), cgz, sum);
        sum = fmaf((float)( s1 >> 24        ), cgw, sum);
    }
    sum = fmaf(KAPPA_F, (float)icnt, sum);

    // ---- block reduce -> global atomic -> last-block finalize ---------------
    sum = warp_sum(sum);
    int lane = t & 31;
    if (lane == 0) sh[w] = sum;
    __syncthreads();
    if (w == 0) {
        float v = (lane < 8) ? sh[lane] : 0.0f;
        v = warp_sum(v);
        if (lane == 0) {
            atomicAdd(&g_acc, (double)v);
            __threadfence();
            unsigned int total = gridDim.x * gridDim.y;
            unsigned int done = atomicInc(&g_ctr, total - 1);   // self-resetting
            if (done == total - 1) {
                double acc = atomicAdd(&g_acc, 0.0);            // atomic read
                // total loss = -( 2*NVOX*B0 + acc ) / (2*NVOX) = -B0 - acc/(2*NVOX)
                out[0] = (float)(-B0_D - acc / (2.0 * (double)NVOX));
                g_acc = 0.0;                                    // reset for next call
            }
        }
    }
}

// ---------------------------------------------------------------------------
extern "C" void kernel_launch(void* const* d_in, const int* in_sizes, int n_in,
                              void* d_out, int out_size)
{
    const float* predF = (const float*)d_in[0];
    const float* predL = (const float*)d_in[1];
    const float* srcF  = (const float*)d_in[2];
    const float* tgtF  = (const float*)d_in[3];
    const float* srcL  = (const float*)d_in[4];
    const float* tgtL  = (const float*)d_in[5];
    const float* gt    = (const float*)d_in[6];
    const float* Ainv  = (const float*)d_in[7];
    const float* tinv  = (const float*)d_in[8];
    float* out = (float*)d_out;

    dim3 bp_grid((NPIX + 255) / 256, 4);      // 64 x 4 = 256 blocks
    bp_kernel<<<bp_grid, 256>>>(predF, predL, srcF, tgtF, srcL, tgtL, Ainv, tinv);

    dim3 rd_grid(VDIM, 4);                    // 512 blocks x 256 threads
    reduce_kernel<<<rd_grid, 256>>>(gt, out);
}

// round 7
// speedup vs baseline: 1.3814x; 1.0171x over previous
#include <cuda_runtime.h>
#include <math.h>

#define S_SAMPLES 512
#define VDIM      128
#define NVOX      (VDIM * VDIM * VDIM)   // 2097152
#define DET       128
#define NPIX      (DET * DET)            // 16384

// 4 binary occupancy volumes, slice = batch*2 + view (view 0 = frontal, 1 = lateral).
// Frontal volumes use TRANSPOSED layout (vx, vz, vy) so warp-lane scatter stores
// (lanes differ in vy) are contiguous. Lateral volumes use natural (vx, vy, vz)
// (lanes differ in vz -> already contiguous).
// Invariant: g_vol is all-zero at entry to kernel_launch (static init + the
// reduce kernel consumes-and-rezeroes every byte it reads).
__device__ __align__(16) unsigned char g_vol[4][NVOX];   // 8 MB
__device__ double       g_acc = 0.0;
__device__ unsigned int g_ctr = 0;

// ---------------------------------------------------------------------------
// Backprojection: one thread per ray; clip sample range to the voxel box,
// then march IN VOXEL SPACE (q(t) affine in t) writing idempotent 1s.
// ---------------------------------------------------------------------------
__global__ void bp_kernel(const float* __restrict__ predF,
                          const float* __restrict__ predL,
                          const float* __restrict__ srcF,
                          const float* __restrict__ tgtF,
                          const float* __restrict__ srcL,
                          const float* __restrict__ tgtL,
                          const float* __restrict__ Ainv,
                          const float* __restrict__ tinv)
{
    int p = blockIdx.x * blockDim.x + threadIdx.x;
    if (p >= NPIX) return;
    int slice = blockIdx.y;          // 0..3
    int view  = slice & 1;           // 0 = frontal, 1 = lateral
    int batch = slice >> 1;

    const float* mask = (view ? predL : predF) + batch * NPIX;
    if (!(mask[p] > 0.5f)) return;   // inactive pixel: nothing to do

    const float* src = view ? srcL : srcF;
    const float* tgt = (view ? tgtL : tgtF) + 3 * p;

    float sx = src[0], sy = src[1], sz = src[2];
    float dx = tgt[0] - sx, dy = tgt[1] - sy, dz = tgt[2] - sz;
    float len = sqrtf(dx * dx + dy * dy + dz * dz);
    float inv = 1.0f / (len + 1e-8f);
    dx *= inv; dy *= inv; dz *= inv;
    float L = len * 2.5f;

    float a00 = Ainv[0], a01 = Ainv[1], a02 = Ainv[2];
    float a10 = Ainv[3], a11 = Ainv[4], a12 = Ainv[5];
    float a20 = Ainv[6], a21 = Ainv[7], a22 = Ainv[8];

    // Voxel-space ray: q(t) = q0 + t*qd   (affine in t)
    float q0x = a00 * sx + a01 * sy + a02 * sz + tinv[0];
    float q0y = a10 * sx + a11 * sy + a12 * sz + tinv[1];
    float q0z = a20 * sx + a21 * sy + a22 * sz + tinv[2];
    float qdx = a00 * dx + a01 * dy + a02 * dz;
    float qdy = a10 * dx + a11 * dy + a12 * dz;
    float qdz = a20 * dx + a21 * dy + a22 * dz;

    const float LOQ = -0.501f;                  // round() valid window with margin
    const float HIQ = (float)VDIM - 0.499f;
    float tlo = 0.0f, thi = L;
    {
        float q0a[3] = {q0x, q0y, q0z};
        float qda[3] = {qdx, qdy, qdz};
        #pragma unroll
        for (int ax = 0; ax < 3; ax++) {
            float q0 = q0a[ax], qd = qda[ax];
            if (fabsf(qd) < 1e-9f) {
                if (q0 < LOQ || q0 > HIQ) { tlo = 1.0f; thi = 0.0f; }
            } else {
                float u1 = (LOQ - q0) / qd;
                float u2 = (HIQ - q0) / qd;
                tlo = fmaxf(tlo, fminf(u1, u2));
                thi = fminf(thi, fmaxf(u1, u2));
            }
        }
    }
    if (thi < tlo) return;

    float dt = L * (1.0f / (S_SAMPLES - 1));
    int klo = max(0,             (int)floorf(tlo / dt) - 2);   // safety margin:
    int khi = min(S_SAMPLES - 1, (int)ceilf (thi / dt) + 2);   // per-sample check authoritative

    // Pre-scale direction by L: q = fma(tv, rd, q0), tv = k/(S-1)
    float rdx = L * qdx, rdy = L * qdy, rdz = L * qdz;
    const float c1 = 1.0f / (S_SAMPLES - 1);

    unsigned char* vol = g_vol[slice];
    for (int k = klo; k <= khi; k++) {
        float tv = (float)k * c1;                      // matches jnp.linspace(0,1,S)
        int vx = __float2int_rn(fmaf(tv, rdx, q0x));   // F2I.rn = ties-to-even (jnp.round)
        int vy = __float2int_rn(fmaf(tv, rdy, q0y));
        int vz = __float2int_rn(fmaf(tv, rdz, q0z));
        if ((unsigned)vx < (unsigned)VDIM &&
            (unsigned)vy < (unsigned)VDIM &&
            (unsigned)vz < (unsigned)VDIM) {
            // view 0 (frontal): transposed (vx, vz, vy) -> lanes contiguous in vy
            // view 1 (lateral): natural    (vx, vy, vz) -> lanes contiguous in vz
            int idx = view ? ((vx * VDIM + vy) * VDIM + vz)
                           : ((vx * VDIM + vz) * VDIM + vy);
            vol[idx] = 1;   // idempotent racy store
        }
    }
}

// ---------------------------------------------------------------------------
// BCE + finalize + volume re-zero, fused. 256 threads, grid (128, 4, 2):
// block = (vx plane, vy quarter (32), vz half (64)) -> 1024 blocks for
// occupancy (512 blocks was grid-limited at ~27/64 warps/SM).
//
// Exact decomposition (sF, sL binary):
//   b[sF+sL] + g*(sF+sL) = B0 + (sF+sL)*(CC + g) + KAPPA*(sF & sL)
// with B0 = log(1-sig(0)), CC = b1-b0, KAPPA = b2-2*b1+b0.
// B0*(2*NVOX) is folded into the finalizer; intersections counted via popc.
//
// ALL global loads are issued up-front (MLP ~7/thread) so the transpose +
// barrier + compute overlap the L2 latency instead of exposing it.
// Every byte of g_vol read here is immediately re-zeroed for the next call.
// ---------------------------------------------------------------------------
#define CC_F    (-0.62011450695827750f)   // b1 - b0
#define KAPPA_F (-0.19355181656647243f)   // b2 - 2*b1 + b0
#define B0_D    (-0.69314718055994531)    // log(0.5)

__device__ __forceinline__ float warp_sum(float v) {
    #pragma unroll
    for (int o = 16; o > 0; o >>= 1) v += __shfl_down_sync(0xffffffffu, v, o);
    return v;
}

#define TROW 68   // smem row stride (vz-half 64 + 4 pad)

__global__ void __launch_bounds__(256)
reduce_kernel(const float* __restrict__ gt, float* __restrict__ out)
{
    __shared__ unsigned char sT0[32 * TROW];   // frontal batch 0: [vy_local][vz_local]
    __shared__ unsigned char sT1[32 * TROW];   // frontal batch 1
    __shared__ float sh[8];

    int vx  = blockIdx.x;            // plane
    int vy0 = blockIdx.y * 32;       // vy quarter
    int vz0 = blockIdx.z * 64;       // vz half
    int t   = threadIdx.x;           // 256 threads

    // ---- phase-1 mapping: both frontal vols, 64 vz rows x 32 vy bytes ------
    // volsel = t>>7; u = t&127: vz row r6 = u>>1, 16B half sub = u&1.
    // Warp: 16 consecutive vz rows x 32 contiguous vy bytes = 16 sectors/512B.
    int volsel = t >> 7;
    int u   = t & 127;
    int r6  = u >> 1;                // vz_local 0..63
    int sub = u & 1;
    size_t go = (size_t)vx * 16384 + (size_t)(vz0 + r6) * 128 + vy0 + sub * 16;
    uint4* pF = reinterpret_cast<uint4*>(g_vol[volsel ? 2 : 0] + go);
    uint4 a = *pF;                   // issue frontal load first

    // ---- phase-2 mapping + issue lateral/gt loads (max MLP) ----------------
    int c  = t & 31;                 // lane
    int w  = t >> 5;                 // warp 0..7
    int vp = c >> 4;                 // vy sub-pair
    int cw = c & 15;                 // vz word within half (vz = vz0+4cw..+3)
    unsigned int l0w[2], l1w[2];
    float4 gv[2];
    int gidx[2];
    #pragma unroll
    for (int ii = 0; ii < 2; ii++) {
        int vyl = w * 4 + 2 * ii + vp;                       // 0..31
        gidx[ii] = vx * 4096 + (vy0 + vyl) * 32 + blockIdx.z * 16 + cw;
        l0w[ii] = reinterpret_cast<const unsigned int*>(g_vol[1])[gidx[ii]];
        l1w[ii] = reinterpret_cast<const unsigned int*>(g_vol[3])[gidx[ii]];
        gv[ii]  = reinterpret_cast<const float4*>(gt)[gidx[ii]];
    }

    // ---- consume-and-reset: zero every byte we just read -------------------
    uint4 z4; z4.x = z4.y = z4.z = z4.w = 0u;
    *pF = z4;
    #pragma unroll
    for (int ii = 0; ii < 2; ii++) {
        reinterpret_cast<unsigned int*>(g_vol[1])[gidx[ii]] = 0u;
        reinterpret_cast<unsigned int*>(g_vol[3])[gidx[ii]] = 0u;
    }

    // ---- smem transpose of frontal (byte column-writes, same-word merge) ---
    unsigned char ab[16];
    *reinterpret_cast<uint4*>(ab) = a;
    unsigned char* sT = volsel ? sT1 : sT0;
    int vybase = sub * 16;
    #pragma unroll
    for (int i = 0; i < 16; i++) {
        sT[(vybase + i) * TROW + r6] = ab[i];
    }
    __syncthreads();

    // ---- compute (registers + smem only; no exposed global latency) --------
    float sum  = 0.0f;
    int   icnt = 0;
    #pragma unroll
    for (int ii = 0; ii < 2; ii++) {
        int vyl = w * 4 + 2 * ii + vp;
        unsigned int f0 = *reinterpret_cast<const unsigned int*>(&sT0[vyl * TROW + 4 * cw]);
        unsigned int f1 = *reinterpret_cast<const unsigned int*>(&sT1[vyl * TROW + 4 * cw]);
        unsigned int s0 = f0 + l0w[ii];          // bytewise sums (each <= 2, no carry)
        unsigned int s1 = f1 + l1w[ii];
        icnt += __popc(f0 & l0w[ii]) + __popc(f1 & l1w[ii]);   // intersections
        float cgx = CC_F + gv[ii].x;
        float cgy = CC_F + gv[ii].y;
        float cgz = CC_F + gv[ii].z;
        float cgw = CC_F + gv[ii].w;
        sum = fmaf((float)( s0        & 255u), cgx, sum);
        sum = fmaf((float)((s0 >>  8) & 255u), cgy, sum);
        sum = fmaf((float)((s0 >> 16) & 255u), cgz, sum);
        sum = fmaf((float)( s0 >> 24        ), cgw, sum);
        sum = fmaf((float)( s1        & 255u), cgx, sum);
        sum = fmaf((float)((s1 >>  8) & 255u), cgy, sum);
        sum = fmaf((float)((s1 >> 16) & 255u), cgz, sum);
        sum = fmaf((float)( s1 >> 24        ), cgw, sum);
    }
    sum = fmaf(KAPPA_F, (float)icnt, sum);

    // ---- block reduce -> global atomic -> last-block finalize --------------
    sum = warp_sum(sum);
    int lane = t & 31;
    if (lane == 0) sh[w] = sum;
    __syncthreads();
    if (w == 0) {
        float v = (lane < 8) ? sh[lane] : 0.0f;
        v = warp_sum(v);
        if (lane == 0) {
            atomicAdd(&g_acc, (double)v);
            __threadfence();
            unsigned int total = gridDim.x * gridDim.y * gridDim.z;
            unsigned int done = atomicInc(&g_ctr, total - 1);   // self-resetting
            if (done == total - 1) {
                double acc = atomicAdd(&g_acc, 0.0);            // atomic read
                // total loss = -( 2*NVOX*B0 + acc ) / (2*NVOX) = -B0 - acc/(2*NVOX)
                out[0] = (float)(-B0_D - acc / (2.0 * (double)NVOX));
                g_acc = 0.0;                                    // reset for next call
            }
        }
    }
}

// ---------------------------------------------------------------------------
extern "C" void kernel_launch(void* const* d_in, const int* in_sizes, int n_in,
                              void* d_out, int out_size)
{
    const float* predF = (const float*)d_in[0];
    const float* predL = (const float*)d_in[1];
    const float* srcF  = (const float*)d_in[2];
    const float* tgtF  = (const float*)d_in[3];
    const float* srcL  = (const float*)d_in[4];
    const float* tgtL  = (const float*)d_in[5];
    const float* gt    = (const float*)d_in[6];
    const float* Ainv  = (const float*)d_in[7];
    const float* tinv  = (const float*)d_in[8];
    float* out = (float*)d_out;

    dim3 bp_grid((NPIX + 255) / 256, 4);      // 64 x 4 = 256 blocks
    bp_kernel<<<bp_grid, 256>>>(predF, predL, srcF, tgtF, srcL, tgtL, Ainv, tinv);

    dim3 rd_grid(VDIM, 4, 2);                 // 1024 blocks x 256 threads
    reduce_kernel<<<rd_grid, 256>>>(gt, out);
}